// round 11
// baseline (speedup 1.0000x reference)
#include <cuda_runtime.h>
#include <cstdint>

// Masked cumsum along dim 1: out[b,:] = cumsum(where(mask, x, 0))
// B=256 rows, N=131072 cols, fp32 x, int32 mask.
//
// R5 topology (one CTA per row, 512 thr, 32 chunks of 4096, warp-owned
// contiguous 256-float segments, ONE __syncthreads per chunk, redundant
// per-warp CTA scan) with the register prefetch replaced by a 3-stage
// cp.async (LDGSTS) smem pipeline:
//   - each thread cp.async.cg's its OWN 2x float4 (x) + 2x int4 (mask) into
//     stage j%3 of a dynamic-smem ring; one commit_group per chunk;
//     wait_group 2 before consuming chunk j (empty commit_groups at the tail
//     keep the pending-count invariant).
//   - self-produced data -> no extra barriers; buffer reuse at j+3 is ordered
//     by program order (LDS at j long complete before j+3's fill).
// In-flight depth per CTA: 48 KB -> 96 KB (the 40 singleton-SM CTAs were
// MLP-limited at ~half their SM's pull rate); prefetch registers freed.
// smem layout per stage (32 KB): x[(warp*2+r)*512 + lane*16], mask at +16 KB
// -> lane-consecutive 16B => conflict-free LDS.128 / cp.async fills.

#define CS_THREADS 512
#define CS_NWARPS  16
#define CS_CHUNK   4096                   // 512 thr * 8 elems
#define CS_NCOLS   131072
#define CS_ITERS   (CS_NCOLS / CS_CHUNK)  // 32
#define CS_STAGES  3
#define STAGE_BYTES 32768                 // 16 KB x + 16 KB mask
#define SMEM_DYN   (CS_STAGES * STAGE_BYTES)  // 98304

__device__ __forceinline__ unsigned smem_u32(const void* p) {
    unsigned a;
    asm("{ .reg .u64 t; cvta.to.shared.u64 t, %1; cvt.u32.u64 %0, t; }"
        : "=r"(a) : "l"(p));
    return a;
}
__device__ __forceinline__ void cp16(unsigned dst, const void* src) {
    asm volatile("cp.async.cg.shared.global [%0], [%1], 16;" :: "r"(dst), "l"(src));
}
__device__ __forceinline__ void cp_commit() {
    asm volatile("cp.async.commit_group;" ::: "memory");
}
__device__ __forceinline__ void cp_wait2() {
    asm volatile("cp.async.wait_group 2;" ::: "memory");
}

extern __shared__ char dynsmem[];

__global__ __launch_bounds__(CS_THREADS, 2)
void masked_cumsum_kernel(const float* __restrict__ x,
                          const int* __restrict__ mask,
                          float* __restrict__ out) {
    __shared__ float shW[2][CS_NWARPS];   // [buf][w] = warp w chunk total

    const int row = blockIdx.x;
    const size_t roff4 = (size_t)row * (CS_NCOLS / 4);
    const float4* __restrict__ x4 = reinterpret_cast<const float4*>(x) + roff4;
    const int4*   __restrict__ m4 = reinterpret_cast<const int4*>(mask) + roff4;
    float4*       __restrict__ o4 = reinterpret_cast<float4*>(out) + roff4;

    const int tid  = threadIdx.x;
    const int lane = tid & 31;
    const int warp = tid >> 5;
    const int wbase = warp * 64 + lane;     // float4 index of warp segment

    // This thread's smem slots (byte offsets within a stage)
    const unsigned sbase = smem_u32(dynsmem);
    const unsigned xo0 = (unsigned)(warp * 2 + 0) * 512u + (unsigned)lane * 16u;
    const unsigned xo1 = (unsigned)(warp * 2 + 1) * 512u + (unsigned)lane * 16u;
    const unsigned mo0 = 16384u + xo0;
    const unsigned mo1 = 16384u + xo1;

    // ---- pipeline prologue: issue chunks 0 and 1 ----
    #pragma unroll
    for (int c = 0; c < CS_STAGES - 1; ++c) {
        const unsigned sb = sbase + (unsigned)c * STAGE_BYTES;
        const int gb = c * (CS_CHUNK / 4) + wbase;
        cp16(sb + xo0, &x4[gb]);
        cp16(sb + xo1, &x4[gb + 32]);
        cp16(sb + mo0, &m4[gb]);
        cp16(sb + mo1, &m4[gb + 32]);
        cp_commit();
    }

    float carry = 0.0f;
    int stage = 0;          // stage holding chunk `it`
    int fstage = CS_STAGES - 1;  // stage to fill with chunk it+STAGES-1

    for (int it = 0; it < CS_ITERS; ++it) {
        // Issue chunk it+2 (or an empty group to keep wait_group accounting)
        if (it + CS_STAGES - 1 < CS_ITERS) {
            const unsigned sb = sbase + (unsigned)fstage * STAGE_BYTES;
            const int gb = (it + CS_STAGES - 1) * (CS_CHUNK / 4) + wbase;
            cp16(sb + xo0, &x4[gb]);
            cp16(sb + xo1, &x4[gb + 32]);
            cp16(sb + mo0, &m4[gb]);
            cp16(sb + mo1, &m4[gb + 32]);
        }
        cp_commit();
        cp_wait2();   // oldest group (chunk `it`) complete

        // Consume chunk `it` from smem (conflict-free LDS.128)
        const unsigned sb = sbase + (unsigned)stage * STAGE_BYTES;
        const float4 xa0 = *reinterpret_cast<const float4*>(dynsmem + (sb - sbase) + xo0);
        const float4 xa1 = *reinterpret_cast<const float4*>(dynsmem + (sb - sbase) + xo1);
        const int4   ma0 = *reinterpret_cast<const int4*>(dynsmem + (sb - sbase) + mo0);
        const int4   ma1 = *reinterpret_cast<const int4*>(dynsmem + (sb - sbase) + mo1);

        // Mask + lane-local inclusive scans (2 ILP rounds)
        float v[2][4];
        v[0][0] = ma0.x ? xa0.x : 0.f; v[0][1] = ma0.y ? xa0.y : 0.f;
        v[0][2] = ma0.z ? xa0.z : 0.f; v[0][3] = ma0.w ? xa0.w : 0.f;
        v[1][0] = ma1.x ? xa1.x : 0.f; v[1][1] = ma1.y ? xa1.y : 0.f;
        v[1][2] = ma1.z ? xa1.z : 0.f; v[1][3] = ma1.w ? xa1.w : 0.f;
        #pragma unroll
        for (int b = 0; b < 2; ++b)
            #pragma unroll
            for (int i = 1; i < 4; ++i) v[b][i] += v[b][i - 1];

        // 2 ILP warp scans
        float lexcl0, lexcl1, T0;
        float warpTotal;
        {
            float ia = v[0][3], ib = v[1][3];
            #pragma unroll
            for (int d = 1; d < 32; d <<= 1) {
                float na = __shfl_up_sync(0xffffffffu, ia, d);
                float nb = __shfl_up_sync(0xffffffffu, ib, d);
                if (lane >= d) { ia += na; ib += nb; }
            }
            lexcl0 = ia - v[0][3];
            lexcl1 = ib - v[1][3];
            T0 = __shfl_sync(0xffffffffu, ia, 31);
            warpTotal = T0 + __shfl_sync(0xffffffffu, ib, 31);
        }

        const int buf = it & 1;
        if (lane == 0) shW[buf][warp] = warpTotal;
        __syncthreads();

        // Redundant-per-warp CTA scan of the 16 warp totals (R5-proven)
        float w = (lane < CS_NWARPS) ? shW[buf][lane] : 0.f;
        float wincl = w;
        #pragma unroll
        for (int d = 1; d < CS_NWARPS; d <<= 1) {
            float n = __shfl_up_sync(0xffffffffu, wincl, d);
            if (lane >= d) wincl += n;
        }
        const float wexcl      = __shfl_sync(0xffffffffu, wincl, warp) -
                                 __shfl_sync(0xffffffffu, w,     warp);
        const float chunkTotal = __shfl_sync(0xffffffffu, wincl, CS_NWARPS - 1);

        const float base0 = carry + wexcl;
        carry += chunkTotal;

        const float baseA = base0 + lexcl0;
        const float baseB = base0 + T0 + lexcl1;
        const int ob = it * (CS_CHUNK / 4) + wbase;
        float4 oa, obv;
        oa.x  = v[0][0] + baseA; oa.y  = v[0][1] + baseA;
        oa.z  = v[0][2] + baseA; oa.w  = v[0][3] + baseA;
        obv.x = v[1][0] + baseB; obv.y = v[1][1] + baseB;
        obv.z = v[1][2] + baseB; obv.w = v[1][3] + baseB;
        __stcs(&o4[ob],      oa);
        __stcs(&o4[ob + 32], obv);

        // advance ring
        stage  = (stage  + 1 == CS_STAGES) ? 0 : stage + 1;
        fstage = (fstage + 1 == CS_STAGES) ? 0 : fstage + 1;
        // No trailing barrier: iter i+2's STS to shW buf is fenced by iter i+1's bar.
    }
}

extern "C" void kernel_launch(void* const* d_in, const int* in_sizes, int n_in,
                              void* d_out, int out_size) {
    const float* x    = (const float*)d_in[0];
    const int*   mask = (const int*)d_in[1];
    float*       out  = (float*)d_out;
    const int rows = out_size / CS_NCOLS;   // 256

    static bool attr_done = false;  // idempotent host-side attribute opt-in
    if (!attr_done) {
        cudaFuncSetAttribute(masked_cumsum_kernel,
                             cudaFuncAttributeMaxDynamicSharedMemorySize, SMEM_DYN);
        attr_done = true;
    }
    masked_cumsum_kernel<<<rows, CS_THREADS, SMEM_DYN>>>(x, mask, out);
}

// round 12
// speedup vs baseline: 1.1435x; 1.1435x over previous
#include <cuda_runtime.h>
#include <cstdint>

// Masked cumsum along dim 1: out[b,:] = cumsum(where(mask, x, 0))
// B=256 rows, N=131072 cols, fp32 x, int32 mask.
//
// FINAL (R5 config, measured best: 63.6us, DRAM 79.5%, ~7.0 TB/s effective).
// One persistent CTA per row, serial carry over 32 chunks of 4096. Each warp
// owns a contiguous 256-float segment per chunk (2 rounds of lane-consecutive
// float4/int4 -> every LDG/STG.128 is a perfect 4-line access). One-chunk-
// ahead register prefetch; streaming cache hints (single-touch data).
// ONE barrier per iteration: after it, every warp redundantly loads all 16
// warp totals from smem (broadcast, conflict-free) and scans them itself
// (4 shfl steps) to get its exclusive prefix + chunk total. Double-buffered
// smem removes the trailing barrier (iter i's reads of buf are fenced from
// iter i+2's writes by iter i+1's barrier).
//
// Alternatives measured and rejected this session: decoupled lookback (110us),
// chained tiles (95us), scalar CTA-scan trees (66us), mbarrier lag-1 pipeline
// (66us), 8192-chunks (69us), 128-thr CTAs (96us), cp.async 3-stage (72us).

#define CS_THREADS 512
#define CS_NWARPS  16
#define CS_CHUNK   4096                   // 512 thr * 8 elems
#define CS_NCOLS   131072
#define CS_ITERS   (CS_NCOLS / CS_CHUNK)  // 32

__device__ __forceinline__ float warp_incl_scan(float v, int lane) {
    #pragma unroll
    for (int d = 1; d < 32; d <<= 1) {
        float n = __shfl_up_sync(0xffffffffu, v, d);
        if (lane >= d) v += n;
    }
    return v;
}

__global__ __launch_bounds__(CS_THREADS, 2)
void masked_cumsum_kernel(const float* __restrict__ x,
                          const int* __restrict__ mask,
                          float* __restrict__ out) {
    __shared__ float sh[2][CS_NWARPS];   // [buf][w] = warp w's chunk total

    const int row = blockIdx.x;
    const size_t roff4 = (size_t)row * (CS_NCOLS / 4);
    const float4* __restrict__ x4 = reinterpret_cast<const float4*>(x) + roff4;
    const int4*   __restrict__ m4 = reinterpret_cast<const int4*>(mask) + roff4;
    float4*       __restrict__ o4 = reinterpret_cast<float4*>(out) + roff4;

    const int tid  = threadIdx.x;
    const int lane = tid & 31;
    const int warp = tid >> 5;
    // Warp w owns floats [w*256, w*256+256) of each chunk:
    // round r (0,1), lane l -> float4 index w*64 + r*32 + l (perfectly coalesced)
    const int wbase = warp * 64 + lane;

    float carry = 0.0f;

    // Prefetch chunk 0
    float4 pa0 = __ldcs(&x4[wbase]);
    float4 pa1 = __ldcs(&x4[wbase + 32]);
    int4   pm0 = __ldcs(&m4[wbase]);
    int4   pm1 = __ldcs(&m4[wbase + 32]);

    for (int it = 0; it < CS_ITERS; ++it) {
        const float4 xa0 = pa0, xa1 = pa1;
        const int4   ma0 = pm0, ma1 = pm1;
        // Issue next chunk's loads immediately; consumed next iteration.
        if (it + 1 < CS_ITERS) {
            const int nb = (it + 1) * (CS_CHUNK / 4) + wbase;
            pa0 = __ldcs(&x4[nb]);
            pa1 = __ldcs(&x4[nb + 32]);
            pm0 = __ldcs(&m4[nb]);
            pm1 = __ldcs(&m4[nb + 32]);
        }

        // Apply mask (each int32 is 0 or 1)
        float v[2][4];
        v[0][0] = ma0.x ? xa0.x : 0.f; v[0][1] = ma0.y ? xa0.y : 0.f;
        v[0][2] = ma0.z ? xa0.z : 0.f; v[0][3] = ma0.w ? xa0.w : 0.f;
        v[1][0] = ma1.x ? xa1.x : 0.f; v[1][1] = ma1.y ? xa1.y : 0.f;
        v[1][2] = ma1.z ? xa1.z : 0.f; v[1][3] = ma1.w ? xa1.w : 0.f;

        // Lane-local inclusive scans (2 independent rounds -> ILP)
        #pragma unroll
        for (int b = 0; b < 2; ++b)
            #pragma unroll
            for (int i = 1; i < 4; ++i) v[b][i] += v[b][i - 1];

        // Warp scan per round (two independent shfl chains), chain round totals
        float lexcl[2], T[2];
        #pragma unroll
        for (int b = 0; b < 2; ++b) {
            const float s = v[b][3];
            const float incl = warp_incl_scan(s, lane);
            lexcl[b] = incl - s;
            T[b] = __shfl_sync(0xffffffffu, incl, 31);
        }
        const float warpTotal = T[0] + T[1];

        const int buf = it & 1;
        if (lane == 0) sh[buf][warp] = warpTotal;
        __syncthreads();

        // Every warp redundantly scans the 16 warp totals (smem broadcast read,
        // 4-step shfl prefix over lanes 0..15). No second barrier, no warp0 wait.
        float w = (lane < CS_NWARPS) ? sh[buf][lane] : 0.f;
        float wincl = w;
        #pragma unroll
        for (int d = 1; d < CS_NWARPS; d <<= 1) {
            float n = __shfl_up_sync(0xffffffffu, wincl, d);
            if (lane >= d) wincl += n;
        }
        const float wexcl      = __shfl_sync(0xffffffffu, wincl, warp) -
                                 __shfl_sync(0xffffffffu, w,     warp);
        const float chunkTotal = __shfl_sync(0xffffffffu, wincl, CS_NWARPS - 1);

        const float base0 = carry + wexcl;
        carry += chunkTotal;

        const float baseA = base0 + lexcl[0];
        const float baseB = base0 + T[0] + lexcl[1];
        const int ob = it * (CS_CHUNK / 4) + wbase;
        float4 oa, obv;
        oa.x  = v[0][0] + baseA; oa.y  = v[0][1] + baseA;
        oa.z  = v[0][2] + baseA; oa.w  = v[0][3] + baseA;
        obv.x = v[1][0] + baseB; obv.y = v[1][1] + baseB;
        obv.z = v[1][2] + baseB; obv.w = v[1][3] + baseB;
        __stcs(&o4[ob],      oa);
        __stcs(&o4[ob + 32], obv);
        // No trailing barrier: iter i+2's STS to this buf is fenced by iter i+1's bar.
    }
}

extern "C" void kernel_launch(void* const* d_in, const int* in_sizes, int n_in,
                              void* d_out, int out_size) {
    const float* x    = (const float*)d_in[0];
    const int*   mask = (const int*)d_in[1];
    float*       out  = (float*)d_out;
    const int rows = out_size / CS_NCOLS;   // 256
    masked_cumsum_kernel<<<rows, CS_THREADS>>>(x, mask, out);
}